// round 9
// baseline (speedup 1.0000x reference)
#include <cuda_runtime.h>
#include <cuda.h>
#include <cstdint>

// BicycleModel: B=65536 vehicles, 256 steps, 4 output planes [B,256] f32.
// R9 = R8 (single-wave TMA design) with the SW64 swizzle-phase bug fixed:
//  - buffer pool is ONE static alignas(1024) shared array (uniform phase)
//  - swizzle column includes runtime base phase ((addr>>7)&3), correct for
//    any >=128B-aligned placement (R8 broke because TMA swizzles by ABSOLUTE
//    smem address and the pool was only 128B-aligned)
//  - TC=16 chunks, SW64 tiles (32v x 16t), ~16.4KB smem -> ~14 blocks/SM
//  - controls: TMA 2D loads, double-buffered, prefetch distance 2
//  - states: single buffer, one 3D TMA store {16,32,4}/chunk, recycled via
//    cp.async.bulk.wait_group.read 0

constexpr int BV  = 65536;
constexpr int NS  = 256;
constexpr int BLK = 32;
constexpr int NCH = 16;            // chunks of 16 timesteps
constexpr int CT4 = 128;           // float4 per 32x16 f32 tile (2KB)

constexpr float DT        = 0.05f;
constexpr float MAX_STEER = 0.52359877559829887f;
constexpr float MAX_SPEED = 100.0f;
constexpr float INV_WB    = 1.0f / 2.7f;

__device__ __forceinline__ uint32_t s2u(const void* p) {
    uint32_t a;
    asm("{ .reg .u64 t; cvta.to.shared.u64 t, %1; cvt.u32.u64 %0, t; }"
        : "=r"(a) : "l"(p));
    return a;
}

__global__ __launch_bounds__(BLK)
void bicycle_kernel(const __grid_constant__ CUtensorMap ta,   // acc  [B,256]
                    const __grid_constant__ CUtensorMap ts,   // steer[B,256]
                    const __grid_constant__ CUtensorMap to,   // out  [4,B,256]
                    const float* __restrict__ sx,
                    const float* __restrict__ sy,
                    const float* __restrict__ syaw,
                    const float* __restrict__ ssp)
{
    // One contiguous pool: cA[2][128] | cS[2][128] | sT[4][128]  (16KB).
    // Every sub-buffer offset is a multiple of 2048B -> same swizzle phase.
    __shared__ alignas(1024) float4 pool[1024];
    __shared__ alignas(8) unsigned long long mb[2];

    float4* cA = pool;                 // [2][128] accel tiles
    float4* cS = pool + 2 * CT4;       // [2][128] steer tiles
    float4* sT = pool + 4 * CT4;       // [4][128] state planes (single buf)

    const int lane = threadIdx.x;
    const int vb   = blockIdx.x * BLK;
    const int b    = vb + lane;

    float x   = sx[b];
    float y   = sy[b];
    float yaw = syaw[b];
    float sp  = ssp[b];

    const uint32_t mb0  = s2u(&mb[0]);
    const uint32_t cAu  = s2u(cA);
    const uint32_t cSu  = s2u(cS);
    const uint32_t sTu  = s2u(sT);

    // SW64 swizzle: f4 column = q ^ (((base>>7) + (v>>1)) & 3).
    // base bits 0-6 are zero (>=128B aligned), so no carry into bits 7-8.
    const int sw = (int)(((cAu >> 7) + (lane >> 1)) & 3);

    if (lane == 0) {
        asm volatile("mbarrier.init.shared.b64 [%0], 1;" :: "r"(mb0) : "memory");
        asm volatile("mbarrier.init.shared.b64 [%0], 1;" :: "r"(mb0 + 8) : "memory");
        asm volatile("fence.proxy.async.shared::cta;" ::: "memory");
    }
    __syncwarp();

#define ISSUE_LOAD(cc) do {                                                   \
        uint32_t mbar = mb0 + ((cc) & 1) * 8;                                 \
        uint32_t da = cAu + ((cc) & 1) * (CT4 * 16);                          \
        uint32_t ds = cSu + ((cc) & 1) * (CT4 * 16);                          \
        asm volatile("mbarrier.arrive.expect_tx.shared.b64 _, [%0], %1;"      \
                     :: "r"(mbar), "r"(4096u) : "memory");                    \
        asm volatile("cp.async.bulk.tensor.2d.shared::cta.global.tile"        \
                     ".mbarrier::complete_tx::bytes [%0], [%1, {%2, %3}], [%4];" \
                     :: "r"(da), "l"(&ta), "r"((cc) * 16), "r"(vb), "r"(mbar) \
                     : "memory");                                             \
        asm volatile("cp.async.bulk.tensor.2d.shared::cta.global.tile"        \
                     ".mbarrier::complete_tx::bytes [%0], [%1, {%2, %3}], [%4];" \
                     :: "r"(ds), "l"(&ts), "r"((cc) * 16), "r"(vb), "r"(mbar) \
                     : "memory");                                             \
    } while (0)

    if (lane == 0) { ISSUE_LOAD(0); ISSUE_LOAD(1); }

#define STEP(A, ST) do {                                                     \
        float fr   = fmaf(0.01f * sp, sp, 0.1f * sp);                        \
        float spn  = fminf(fmaxf(fmaf(DT, (A) - fr, sp), 0.0f), MAX_SPEED);  \
        float sc   = fminf(fmaxf((ST), -MAX_STEER), MAX_STEER);              \
        float angv = sp * __tanf(sc) * INV_WB;                               \
        float sn, cc2;                                                       \
        __sincosf(yaw, &sn, &cc2);                                           \
        x   = fmaf(sp * cc2, DT, x);                                         \
        y   = fmaf(sp * sn, DT, y);                                          \
        yaw = fmaf(angv, DT, yaw);                                           \
        sp  = spn;                                                           \
    } while (0)

    for (int c = 0; c < NCH; ++c) {
        const int buf = c & 1;
        const int ph  = (c >> 1) & 1;

        // Wait for this chunk's control tiles (acquire).
        {
            uint32_t mbar = mb0 + buf * 8;
            uint32_t done;
            asm volatile("{\n\t.reg .pred p;\n\t"
                         "mbarrier.try_wait.parity.acquire.cta.shared::cta.b64 p, [%1], %2;\n\t"
                         "selp.b32 %0, 1, 0, p;\n\t}"
                         : "=r"(done) : "r"(mbar), "r"(ph) : "memory");
            if (!done) {
                asm volatile("{\n\t.reg .pred P1;\n\t"
                             "W%=:\n\t"
                             "mbarrier.try_wait.parity.acquire.cta.shared::cta.b64 P1, [%0], %1, 0x989680;\n\t"
                             "@P1 bra.uni D%=;\n\t"
                             "bra.uni W%=;\n\t"
                             "D%=:\n\t}"
                             :: "r"(mbar), "r"(ph) : "memory");
            }
        }

        // Recycle the single state buffer: prior chunk's TMA store must be
        // done READING smem before we overwrite it.
        if (c >= 1) {
            if (lane == 0)
                asm volatile("cp.async.bulk.wait_group.read 0;" ::: "memory");
            __syncwarp();
        }

        const float4* A4p = cA + buf * CT4;
        const float4* S4p = cS + buf * CT4;

#pragma unroll
        for (int q = 0; q < 4; ++q) {
            const int si = lane * 4 + (q ^ sw);
            float4 A4 = A4p[si];
            float4 S4 = S4p[si];
            float4 X, Y, W, S;
            X.x = x; Y.x = y; W.x = yaw; S.x = sp;  STEP(A4.x, S4.x);
            X.y = x; Y.y = y; W.y = yaw; S.y = sp;  STEP(A4.y, S4.y);
            X.z = x; Y.z = y; W.z = yaw; S.z = sp;  STEP(A4.z, S4.z);
            X.w = x; Y.w = y; W.w = yaw; S.w = sp;  STEP(A4.w, S4.w);
            sT[si]       = X;           // plane 0: x
            sT[128 + si] = Y;           // plane 1: y
            sT[256 + si] = W;           // plane 2: yaw
            sT[384 + si] = S;           // plane 3: speed
        }
        __syncwarp();

        // One 3D TMA store covers all 4 planes; then prefetch controls c+2.
        if (lane == 0) {
            asm volatile("fence.proxy.async.shared::cta;" ::: "memory");
            asm volatile("cp.async.bulk.tensor.3d.global.shared::cta.tile.bulk_group"
                         " [%0, {%1, %2, %3}], [%4];"
                         :: "l"(&to), "r"(c * 16), "r"(vb), "r"(0), "r"(sTu)
                         : "memory");
            asm volatile("cp.async.bulk.commit_group;" ::: "memory");
            if (c + 2 < NCH) ISSUE_LOAD(c + 2);
        }
        __syncwarp();
    }

    if (lane == 0)
        asm volatile("cp.async.bulk.wait_group 0;" ::: "memory");
#undef STEP
#undef ISSUE_LOAD
}

// ---------------- host ----------------

typedef CUresult (*EncodeFn)(CUtensorMap*, CUtensorMapDataType, cuuint32_t, void*,
                             const cuuint64_t*, const cuuint64_t*,
                             const cuuint32_t*, const cuuint32_t*,
                             CUtensorMapInterleave, CUtensorMapSwizzle,
                             CUtensorMapL2promotion, CUtensorMapFloatOOBfill);

extern "C" void kernel_launch(void* const* d_in, const int* in_sizes, int n_in,
                              void* d_out, int out_size)
{
    (void)in_sizes; (void)n_in; (void)out_size;

    void* fptr = nullptr;
    cudaDriverEntryPointQueryResult qr;
    cudaGetDriverEntryPointByVersion("cuTensorMapEncodeTiled", &fptr, 12000,
                                     cudaEnableDefault, &qr);
    EncodeFn encode = (EncodeFn)fptr;

    CUtensorMap ta, ts, to;

    // controls: [B, 256] f32, tile 16x32, SW64 (64B rows)
    {
        cuuint64_t dims[2]    = {NS, BV};
        cuuint64_t strides[1] = {NS * 4};
        cuuint32_t box[2]     = {16, 32};
        cuuint32_t es[2]      = {1, 1};
        encode(&ta, CU_TENSOR_MAP_DATA_TYPE_FLOAT32, 2, d_in[4], dims, strides,
               box, es, CU_TENSOR_MAP_INTERLEAVE_NONE, CU_TENSOR_MAP_SWIZZLE_64B,
               CU_TENSOR_MAP_L2_PROMOTION_L2_128B, CU_TENSOR_MAP_FLOAT_OOB_FILL_NONE);
        encode(&ts, CU_TENSOR_MAP_DATA_TYPE_FLOAT32, 2, d_in[5], dims, strides,
               box, es, CU_TENSOR_MAP_INTERLEAVE_NONE, CU_TENSOR_MAP_SWIZZLE_64B,
               CU_TENSOR_MAP_L2_PROMOTION_L2_128B, CU_TENSOR_MAP_FLOAT_OOB_FILL_NONE);
    }
    // output: [4, B, 256] f32, tile 16x32x4, SW64
    {
        cuuint64_t dims[3]    = {NS, BV, 4};
        cuuint64_t strides[2] = {NS * 4, (cuuint64_t)BV * NS * 4};
        cuuint32_t box[3]     = {16, 32, 4};
        cuuint32_t es[3]      = {1, 1, 1};
        encode(&to, CU_TENSOR_MAP_DATA_TYPE_FLOAT32, 3, d_out, dims, strides,
               box, es, CU_TENSOR_MAP_INTERLEAVE_NONE, CU_TENSOR_MAP_SWIZZLE_64B,
               CU_TENSOR_MAP_L2_PROMOTION_L2_128B, CU_TENSOR_MAP_FLOAT_OOB_FILL_NONE);
    }

    bicycle_kernel<<<BV / BLK, BLK>>>(
        ta, ts, to,
        (const float*)d_in[0], (const float*)d_in[1],
        (const float*)d_in[2], (const float*)d_in[3]);
}

// round 10
// speedup vs baseline: 1.0563x; 1.0563x over previous
#include <cuda_runtime.h>
#include <cuda.h>
#include <cstdint>

// BicycleModel: B=65536 vehicles, 256 steps, 4 output planes [B,256] f32.
// R10 = R9 + double-buffered state tiles (R7's store pipelining):
//  - TC=16 chunks, SW64 tiles (32v x 16t f32), runtime swizzle phase
//  - smem 24KB/block -> 9 blocks/SM (1.54 waves)
//  - controls: TMA 2D loads, double-buffered, prefetch distance 2
//  - states: DOUBLE buffer, one 3D TMA store {16,32,4}/chunk, recycled with
//    cp.async.bulk.wait_group.read 1 (store overlaps next chunk's compute)

constexpr int BV  = 65536;
constexpr int NS  = 256;
constexpr int BLK = 32;
constexpr int NCH = 16;            // chunks of 16 timesteps
constexpr int CT4 = 128;           // float4 per 32x16 f32 tile (2KB)

constexpr float DT        = 0.05f;
constexpr float MAX_STEER = 0.52359877559829887f;
constexpr float MAX_SPEED = 100.0f;
constexpr float INV_WB    = 1.0f / 2.7f;

__device__ __forceinline__ uint32_t s2u(const void* p) {
    uint32_t a;
    asm("{ .reg .u64 t; cvta.to.shared.u64 t, %1; cvt.u32.u64 %0, t; }"
        : "=r"(a) : "l"(p));
    return a;
}

__global__ __launch_bounds__(BLK)
void bicycle_kernel(const __grid_constant__ CUtensorMap ta,   // acc  [B,256]
                    const __grid_constant__ CUtensorMap ts,   // steer[B,256]
                    const __grid_constant__ CUtensorMap to,   // out  [4,B,256]
                    const float* __restrict__ sx,
                    const float* __restrict__ sy,
                    const float* __restrict__ syaw,
                    const float* __restrict__ ssp)
{
    // Pool: cA[2][128] | cS[2][128] | sT[2][4][128]  = 24KB.
    // All sub-buffers at 2KB multiples -> uniform SW64 phase.
    __shared__ alignas(1024) float4 pool[1536];
    __shared__ alignas(8) unsigned long long mb[2];

    float4* cA = pool;                 // [2][128] accel tiles
    float4* cS = pool + 2 * CT4;       // [2][128] steer tiles
    float4* sT = pool + 4 * CT4;       // [2][4][128] state planes

    const int lane = threadIdx.x;
    const int vb   = blockIdx.x * BLK;
    const int b    = vb + lane;

    float x   = sx[b];
    float y   = sy[b];
    float yaw = syaw[b];
    float sp  = ssp[b];

    const uint32_t mb0 = s2u(&mb[0]);
    const uint32_t cAu = s2u(cA);
    const uint32_t cSu = s2u(cS);
    const uint32_t sTu = s2u(sT);

    // SW64 swizzle: f4 column = q ^ (((base>>7) + (v>>1)) & 3).
    // Base bits 0-6 are zero (>=128B aligned): no carry into bits 7-8.
    const int sw = (int)(((cAu >> 7) + (lane >> 1)) & 3);

    if (lane == 0) {
        asm volatile("mbarrier.init.shared.b64 [%0], 1;" :: "r"(mb0) : "memory");
        asm volatile("mbarrier.init.shared.b64 [%0], 1;" :: "r"(mb0 + 8) : "memory");
        asm volatile("fence.proxy.async.shared::cta;" ::: "memory");
    }
    __syncwarp();

#define ISSUE_LOAD(cc) do {                                                   \
        uint32_t mbar = mb0 + ((cc) & 1) * 8;                                 \
        uint32_t da = cAu + ((cc) & 1) * (CT4 * 16);                          \
        uint32_t ds = cSu + ((cc) & 1) * (CT4 * 16);                          \
        asm volatile("mbarrier.arrive.expect_tx.shared.b64 _, [%0], %1;"      \
                     :: "r"(mbar), "r"(4096u) : "memory");                    \
        asm volatile("cp.async.bulk.tensor.2d.shared::cta.global.tile"        \
                     ".mbarrier::complete_tx::bytes [%0], [%1, {%2, %3}], [%4];" \
                     :: "r"(da), "l"(&ta), "r"((cc) * 16), "r"(vb), "r"(mbar) \
                     : "memory");                                             \
        asm volatile("cp.async.bulk.tensor.2d.shared::cta.global.tile"        \
                     ".mbarrier::complete_tx::bytes [%0], [%1, {%2, %3}], [%4];" \
                     :: "r"(ds), "l"(&ts), "r"((cc) * 16), "r"(vb), "r"(mbar) \
                     : "memory");                                             \
    } while (0)

    if (lane == 0) { ISSUE_LOAD(0); ISSUE_LOAD(1); }

#define STEP(A, ST) do {                                                     \
        float fr   = fmaf(0.01f * sp, sp, 0.1f * sp);                        \
        float spn  = fminf(fmaxf(fmaf(DT, (A) - fr, sp), 0.0f), MAX_SPEED);  \
        float sc   = fminf(fmaxf((ST), -MAX_STEER), MAX_STEER);              \
        float angv = sp * __tanf(sc) * INV_WB;                               \
        float sn, cc2;                                                       \
        __sincosf(yaw, &sn, &cc2);                                           \
        x   = fmaf(sp * cc2, DT, x);                                         \
        y   = fmaf(sp * sn, DT, y);                                          \
        yaw = fmaf(angv, DT, yaw);                                           \
        sp  = spn;                                                           \
    } while (0)

    for (int c = 0; c < NCH; ++c) {
        const int buf = c & 1;
        const int ph  = (c >> 1) & 1;

        // Wait for this chunk's control tiles (acquire).
        {
            uint32_t mbar = mb0 + buf * 8;
            uint32_t done;
            asm volatile("{\n\t.reg .pred p;\n\t"
                         "mbarrier.try_wait.parity.acquire.cta.shared::cta.b64 p, [%1], %2;\n\t"
                         "selp.b32 %0, 1, 0, p;\n\t}"
                         : "=r"(done) : "r"(mbar), "r"(ph) : "memory");
            if (!done) {
                asm volatile("{\n\t.reg .pred P1;\n\t"
                             "W%=:\n\t"
                             "mbarrier.try_wait.parity.acquire.cta.shared::cta.b64 P1, [%0], %1, 0x989680;\n\t"
                             "@P1 bra.uni D%=;\n\t"
                             "bra.uni W%=;\n\t"
                             "D%=:\n\t}"
                             :: "r"(mbar), "r"(ph) : "memory");
            }
        }

        // State buffer reuse: chunk c-2's TMA store (same buffer) must be done
        // READING smem; tolerate one outstanding group (chunk c-1) -> overlap.
        if (c >= 2) {
            if (lane == 0)
                asm volatile("cp.async.bulk.wait_group.read 1;" ::: "memory");
            __syncwarp();
        }

        const float4* A4p = cA + buf * CT4;
        const float4* S4p = cS + buf * CT4;
        float4* P = sT + buf * (4 * CT4);

#pragma unroll
        for (int q = 0; q < 4; ++q) {
            const int si = lane * 4 + (q ^ sw);
            float4 A4 = A4p[si];
            float4 S4 = S4p[si];
            float4 X, Y, W, S;
            X.x = x; Y.x = y; W.x = yaw; S.x = sp;  STEP(A4.x, S4.x);
            X.y = x; Y.y = y; W.y = yaw; S.y = sp;  STEP(A4.y, S4.y);
            X.z = x; Y.z = y; W.z = yaw; S.z = sp;  STEP(A4.z, S4.z);
            X.w = x; Y.w = y; W.w = yaw; S.w = sp;  STEP(A4.w, S4.w);
            P[si]       = X;            // plane 0: x
            P[128 + si] = Y;            // plane 1: y
            P[256 + si] = W;            // plane 2: yaw
            P[384 + si] = S;            // plane 3: speed
        }
        __syncwarp();

        // One 3D TMA store covers all 4 planes; then prefetch controls c+2.
        if (lane == 0) {
            asm volatile("fence.proxy.async.shared::cta;" ::: "memory");
            uint32_t src = sTu + buf * (4 * CT4 * 16);
            asm volatile("cp.async.bulk.tensor.3d.global.shared::cta.tile.bulk_group"
                         " [%0, {%1, %2, %3}], [%4];"
                         :: "l"(&to), "r"(c * 16), "r"(vb), "r"(0), "r"(src)
                         : "memory");
            asm volatile("cp.async.bulk.commit_group;" ::: "memory");
            if (c + 2 < NCH) ISSUE_LOAD(c + 2);
        }
        __syncwarp();
    }

    if (lane == 0)
        asm volatile("cp.async.bulk.wait_group 0;" ::: "memory");
#undef STEP
#undef ISSUE_LOAD
}

// ---------------- host ----------------

typedef CUresult (*EncodeFn)(CUtensorMap*, CUtensorMapDataType, cuuint32_t, void*,
                             const cuuint64_t*, const cuuint64_t*,
                             const cuuint32_t*, const cuuint32_t*,
                             CUtensorMapInterleave, CUtensorMapSwizzle,
                             CUtensorMapL2promotion, CUtensorMapFloatOOBfill);

extern "C" void kernel_launch(void* const* d_in, const int* in_sizes, int n_in,
                              void* d_out, int out_size)
{
    (void)in_sizes; (void)n_in; (void)out_size;

    void* fptr = nullptr;
    cudaDriverEntryPointQueryResult qr;
    cudaGetDriverEntryPointByVersion("cuTensorMapEncodeTiled", &fptr, 12000,
                                     cudaEnableDefault, &qr);
    EncodeFn encode = (EncodeFn)fptr;

    CUtensorMap ta, ts, to;

    // controls: [B, 256] f32, tile 16x32, SW64 (64B rows)
    {
        cuuint64_t dims[2]    = {NS, BV};
        cuuint64_t strides[1] = {NS * 4};
        cuuint32_t box[2]     = {16, 32};
        cuuint32_t es[2]      = {1, 1};
        encode(&ta, CU_TENSOR_MAP_DATA_TYPE_FLOAT32, 2, d_in[4], dims, strides,
               box, es, CU_TENSOR_MAP_INTERLEAVE_NONE, CU_TENSOR_MAP_SWIZZLE_64B,
               CU_TENSOR_MAP_L2_PROMOTION_L2_128B, CU_TENSOR_MAP_FLOAT_OOB_FILL_NONE);
        encode(&ts, CU_TENSOR_MAP_DATA_TYPE_FLOAT32, 2, d_in[5], dims, strides,
               box, es, CU_TENSOR_MAP_INTERLEAVE_NONE, CU_TENSOR_MAP_SWIZZLE_64B,
               CU_TENSOR_MAP_L2_PROMOTION_L2_128B, CU_TENSOR_MAP_FLOAT_OOB_FILL_NONE);
    }
    // output: [4, B, 256] f32, tile 16x32x4, SW64
    {
        cuuint64_t dims[3]    = {NS, BV, 4};
        cuuint64_t strides[2] = {NS * 4, (cuuint64_t)BV * NS * 4};
        cuuint32_t box[3]     = {16, 32, 4};
        cuuint32_t es[3]      = {1, 1, 1};
        encode(&to, CU_TENSOR_MAP_DATA_TYPE_FLOAT32, 3, d_out, dims, strides,
               box, es, CU_TENSOR_MAP_INTERLEAVE_NONE, CU_TENSOR_MAP_SWIZZLE_64B,
               CU_TENSOR_MAP_L2_PROMOTION_L2_128B, CU_TENSOR_MAP_FLOAT_OOB_FILL_NONE);
    }

    bicycle_kernel<<<BV / BLK, BLK>>>(
        ta, ts, to,
        (const float*)d_in[0], (const float*)d_in[1],
        (const float*)d_in[2], (const float*)d_in[3]);
}